// round 5
// baseline (speedup 1.0000x reference)
#include <cuda_runtime.h>
#include <math.h>
#include <stdint.h>

// Problem: B=64, T=1024, D=512, H=512
//   xw = x @ W[:512] + b              (65536x512x512 GEMM)
//   h_t = tanh(xw_t + h_{t-1} @ Wh)   scan over T=1024
//
// Phase 1: FFMA2 (packed f32x2) tiled GEMM -> g_xw scratch
// Phase 2: 16 groups x 8-CTA clusters. Group = 4 batch rows x 512 features;
//          CTA = 64 feature cols. Handshake flags go over the cluster DSMEM
//          fabric into consumer smem (local ~35cyc polling); h data goes
//          through L2 (coalesced 1KB/warp pulls). No cluster barriers, no
//          atomics, no broadcast pushes in the loop.

__device__ float g_xw[64u * 1024u * 512u];  // 128 MB scratch: [b][t][h]
__device__ float g_h[2][16][2048];          // [buf][group][feature*4+row]

#define FMA2(d, a, b, c) \
    asm("fma.rn.f32x2 %0, %1, %2, %3;" : "=l"(d) : "l"(a), "l"(b), "l"(c))
#define PACK2(d, lo, hi) \
    asm("mov.b64 %0, {%1, %2};" : "=l"(d) : "f"(lo), "f"(hi))
#define UNPACK2(lo, hi, v) \
    asm("mov.b64 {%0, %1}, %2;" : "=f"(lo), "=f"(hi) : "l"(v))

// ---------------------------------------------------------------------------
// Phase 1: g_xw[m][n] = sum_k x[m][k] * W[k][n] + b[n]
// ---------------------------------------------------------------------------
__global__ __launch_bounds__(256) void xw_gemm(const float* __restrict__ x,
                                               const float* __restrict__ W,
                                               const float* __restrict__ bias) {
    __shared__ __align__(16) float Ast[16][132];
    __shared__ __align__(16) float Bs[16][128];

    const int tid = threadIdx.x;
    const int bn = blockIdx.x & 3;
    const int bm = blockIdx.x >> 2;
    const int row0 = bm << 7;
    const int n0 = bn << 7;
    const int mt = tid >> 4;
    const int nt = tid & 15;

    unsigned long long acc[4][8];
#pragma unroll
    for (int p = 0; p < 4; p++)
#pragma unroll
        for (int j = 0; j < 8; j++) acc[p][j] = 0ULL;

    for (int kt = 0; kt < 512; kt += 16) {
#pragma unroll
        for (int it = 0; it < 2; it++) {
            int idx = tid + (it << 8);
            int m = idx >> 2;
            int kq = (idx & 3) << 2;
            float4 v = *(const float4*)(x + (size_t)(row0 + m) * 512 + kt + kq);
            Ast[kq + 0][m] = v.x;
            Ast[kq + 1][m] = v.y;
            Ast[kq + 2][m] = v.z;
            Ast[kq + 3][m] = v.w;
        }
#pragma unroll
        for (int it = 0; it < 2; it++) {
            int idx = tid + (it << 8);
            int k = idx >> 5;
            int nq = (idx & 31) << 2;
            *(float4*)(&Bs[k][nq]) =
                *(const float4*)(W + (size_t)(kt + k) * 512 + n0 + nq);
        }
        __syncthreads();
#pragma unroll
        for (int k = 0; k < 16; k++) {
            ulonglong2 aA = *(const ulonglong2*)(&Ast[k][4 * mt]);
            ulonglong2 aB = *(const ulonglong2*)(&Ast[k][64 + 4 * mt]);
            float4 b0 = *(const float4*)(&Bs[k][4 * nt]);
            float4 b1 = *(const float4*)(&Bs[k][64 + 4 * nt]);
            unsigned long long bb[8];
            PACK2(bb[0], b0.x, b0.x);
            PACK2(bb[1], b0.y, b0.y);
            PACK2(bb[2], b0.z, b0.z);
            PACK2(bb[3], b0.w, b0.w);
            PACK2(bb[4], b1.x, b1.x);
            PACK2(bb[5], b1.y, b1.y);
            PACK2(bb[6], b1.z, b1.z);
            PACK2(bb[7], b1.w, b1.w);
#pragma unroll
            for (int j = 0; j < 8; j++) {
                FMA2(acc[0][j], aA.x, bb[j], acc[0][j]);
                FMA2(acc[1][j], aA.y, bb[j], acc[1][j]);
                FMA2(acc[2][j], aB.x, bb[j], acc[2][j]);
                FMA2(acc[3][j], aB.y, bb[j], acc[3][j]);
            }
        }
        __syncthreads();
    }

    float bv[8];
#pragma unroll
    for (int j = 0; j < 4; j++) {
        bv[j] = bias[n0 + 4 * nt + j];
        bv[4 + j] = bias[n0 + 64 + 4 * nt + j];
    }
    float res[8][8];
#pragma unroll
    for (int p = 0; p < 4; p++)
#pragma unroll
        for (int j = 0; j < 8; j++) {
            float lo, hi;
            UNPACK2(lo, hi, acc[p][j]);
            res[2 * p][j] = lo + bv[j];
            res[2 * p + 1][j] = hi + bv[j];
        }
#pragma unroll
    for (int rI = 0; rI < 8; rI++) {
        int lrow = (rI < 4) ? (4 * mt + rI) : (64 + 4 * mt + (rI - 4));
        size_t base = (size_t)(row0 + lrow) * 512 + n0;
        float4 s0 = make_float4(res[rI][0], res[rI][1], res[rI][2], res[rI][3]);
        float4 s1 = make_float4(res[rI][4], res[rI][5], res[rI][6], res[rI][7]);
        *(float4*)(g_xw + base + 4 * nt) = s0;
        *(float4*)(g_xw + base + 64 + 4 * nt) = s1;
    }
}

// ---------------------------------------------------------------------------
// Phase 2: clustered scan, DSMEM flag fabric + L2 data.
//   CTA (g = bid>>3, rank): rows r0=g*4, cols c0=rank*64.
//   Thread: cp = tid&31 -> cols c0+2cp, c0+2cp+1 ; ks = tid>>5 -> k-chunk
//   [64ks, 64ks+64) == the 64 features produced by peer CTA `ks`.
//   Step: warp polls LOCAL smem flag[ks] (written remotely by peer ks) ->
//         1KB L2 refill -> 64-iter FMA2 (wpk = {w_even,w_odd}) ->
//         smem k-reduce -> tanh -> out + g_h publish -> 8 remote flag stores.
// ---------------------------------------------------------------------------
__global__ __launch_bounds__(256, 1) __cluster_dims__(8, 1, 1)
void rnn_scan(const float* __restrict__ W, float* __restrict__ out) {
    // per-warp slab: 64 features x 48B ({h0,h0,h1,h1}{h2,h2,h3,h3} + 16B pad)
    __shared__ __align__(16) float slab[8][64 * 12];  // 24 KB
    __shared__ float red[8][4][68];                   // [kchunk][row][col]
    __shared__ unsigned int sflags[8];                // written by peers

    const int bid = blockIdx.x;
    const int g = bid >> 3;   // group 0..15
    const int r0 = g << 2;    // 4 batch rows
    const int tid = threadIdx.x;
    const int cp = tid & 31;  // col-pair within CTA tile
    const int ks = tid >> 5;  // warp id == k-chunk (64 k each)

    uint32_t rank;
    asm("mov.u32 %0, %%cluster_ctarank;" : "=r"(rank));
    const int c0 = ((int)rank) << 6;  // 64 cols per CTA

    // zero local flags, then cluster-sync so no peer's step-0 flag can race
    if (tid < 8) sflags[tid] = 0u;
    __syncthreads();
    asm volatile("barrier.cluster.arrive.aligned;" ::: "memory");
    asm volatile("barrier.cluster.wait.aligned;" ::: "memory");

    // smem addresses for flag fabric
    uint32_t myflag_addr;  // &sflags[ks] (polled by this warp)
    asm("{ .reg .u64 t; cvta.to.shared.u64 t, %1; cvt.u32.u64 %0, t; }"
        : "=r"(myflag_addr)
        : "l"((void*)&sflags[ks]));
    uint32_t peer_flag = 0;  // thread tid<8: &sflags[rank] inside peer `tid`
    if (tid < 8) {
        uint32_t local_slot;
        asm("{ .reg .u64 t; cvta.to.shared.u64 t, %1; cvt.u32.u64 %0, t; }"
            : "=r"(local_slot)
            : "l"((void*)&sflags[rank]));
        asm("mapa.shared::cluster.u32 %0, %1, %2;"
            : "=r"(peer_flag)
            : "r"(local_slot), "r"(tid));
    }

    // Wh slice: wpk[j] = {W[512+64ks+j][c0+2cp], W[512+64ks+j][c0+2cp+1]}
    unsigned long long wpk[64];
#pragma unroll
    for (int j = 0; j < 64; j++) {
        float2 w2 =
            *(const float2*)&W[(size_t)(512 + (ks << 6) + j) * 512 + c0 +
                               (cp << 1)];
        PACK2(wpk[j], w2.x, w2.y);
    }

    const int rr = tid >> 6;  // epilogue row 0..3
    const int cc = tid & 63;  // epilogue col 0..63
    float* const sl = &slab[ks][0];

    for (int t = 0; t < 1024; t++) {
        // xw prefetch — overlaps poll + refill + mainloop
        float xwv =
            g_xw[((size_t)(r0 + rr) * 1024 + (size_t)t) * 512 + c0 + cc];

        unsigned long long a0 = 0ULL, a1 = 0ULL, a2 = 0ULL, a3 = 0ULL;
        if (t > 0) {
            // local poll: peer `ks` bumped our sflags[ks] to >= t
            unsigned int fv;
            do {
                asm volatile("ld.acquire.cluster.shared::cta.u32 %0, [%1];"
                             : "=r"(fv)
                             : "r"(myflag_addr)
                             : "memory");
            } while (fv < (unsigned int)t);

            // refill this warp's 64 features (1KB, coalesced from L2),
            // stored duplicated for {h,h} broadcast
            const float4* src =
                (const float4*)&g_h[t & 1][g][(unsigned)(ks << 8)];
            float4 v0 = src[cp];        // feature cp, rows 0..3
            float4 v1 = src[cp + 32];   // feature cp+32
            *(float4*)(sl + 12 * cp) =
                make_float4(v0.x, v0.x, v0.y, v0.y);
            *(float4*)(sl + 12 * cp + 4) =
                make_float4(v0.z, v0.z, v0.w, v0.w);
            *(float4*)(sl + 12 * (cp + 32)) =
                make_float4(v1.x, v1.x, v1.y, v1.y);
            *(float4*)(sl + 12 * (cp + 32) + 4) =
                make_float4(v1.z, v1.z, v1.w, v1.w);
            __syncwarp();

#pragma unroll
            for (int j = 0; j < 64; j++) {
                ulonglong2 h01 = *(const ulonglong2*)(sl + 12 * j);
                ulonglong2 h23 = *(const ulonglong2*)(sl + 12 * j + 4);
                FMA2(a0, h01.x, wpk[j], a0);  // row 0, cols {e,o}
                FMA2(a1, h01.y, wpk[j], a1);  // row 1
                FMA2(a2, h23.x, wpk[j], a2);  // row 2
                FMA2(a3, h23.y, wpk[j], a3);  // row 3
            }
        }
        // partials -> red (packed pairs land as [col] floats)
        *(unsigned long long*)&red[ks][0][cp << 1] = a0;
        *(unsigned long long*)&red[ks][1][cp << 1] = a1;
        *(unsigned long long*)&red[ks][2][cp << 1] = a2;
        *(unsigned long long*)&red[ks][3][cp << 1] = a3;
        __syncthreads();

        float sum = xwv;
#pragma unroll
        for (int q = 0; q < 8; q++) sum += red[q][rr][cc];
        float v = tanhf(sum);

        out[((size_t)(r0 + rr) * 1024 + (size_t)t) * 512 + c0 + cc] = v;

        if (t < 1023) {
            // publish h(t+1): [feature*4 + row] so consumer pulls are float4
            g_h[(t + 1) & 1][g][((c0 + cc) << 2) + rr] = v;
            __syncthreads();  // h-stores + red reads complete CTA-wide
            if (tid < 8) {
                // release-store step stamp into peer tid's sflags[rank]
                asm volatile(
                    "st.release.cluster.shared::cluster.u32 [%0], %1;" ::"r"(
                        peer_flag),
                    "r"((unsigned int)(t + 1))
                    : "memory");
            }
        }
    }
}

// ---------------------------------------------------------------------------
extern "C" void kernel_launch(void* const* d_in, const int* in_sizes, int n_in,
                              void* d_out, int out_size) {
    const float* x = (const float*)d_in[0];  // (64, 1024, 512) f32
    const float* W = (const float*)d_in[1];  // (1024, 512) f32
    const float* b = (const float*)d_in[2];  // (512,) f32
    float* out = (float*)d_out;              // (64, 1024, 512) f32

    xw_gemm<<<2048, 256>>>(x, W, b);
    rnn_scan<<<128, 256>>>(W, out);
}

// round 6
// speedup vs baseline: 1.1869x; 1.1869x over previous
#include <cuda_runtime.h>
#include <math.h>
#include <stdint.h>

// Problem: B=64, T=1024, D=512, H=512
//   xw = x @ W[:512] + b              (65536x512x512 GEMM)
//   h_t = tanh(xw_t + h_{t-1} @ Wh)   scan over T=1024
//
// Phase 1: FFMA2 (packed f32x2) tiled GEMM -> g_xw scratch
// Phase 2: 16 groups x 8-CTA clusters; CTA = 4 rows x 64 cols.
//   h exchange: st.async remote-smem pushes w/ mbarrier complete_tx
//   (weak stores, HW tx count); consumers wait per-producer LOCAL
//   mbarriers at cta scope (no cluster-scope fences -> no L1D flush).

__device__ float g_xw[64u * 1024u * 512u];  // 128 MB scratch: [b][t][h]

#define FMA2(d, a, b, c) \
    asm("fma.rn.f32x2 %0, %1, %2, %3;" : "=l"(d) : "l"(a), "l"(b), "l"(c))
#define ADDF2(d, a, b) \
    asm("add.rn.f32x2 %0, %1, %2;" : "=l"(d) : "l"(a), "l"(b))
#define PACK2(d, lo, hi) \
    asm("mov.b64 %0, {%1, %2};" : "=l"(d) : "f"(lo), "f"(hi))
#define UNPACK2(lo, hi, v) \
    asm("mov.b64 {%0, %1}, %2;" : "=f"(lo), "=f"(hi) : "l"(v))

// ---------------------------------------------------------------------------
// Phase 1: g_xw[m][n] = sum_k x[m][k] * W[k][n] + b[n]
// ---------------------------------------------------------------------------
__global__ __launch_bounds__(256) void xw_gemm(const float* __restrict__ x,
                                               const float* __restrict__ W,
                                               const float* __restrict__ bias) {
    __shared__ __align__(16) float Ast[16][132];
    __shared__ __align__(16) float Bs[16][128];

    const int tid = threadIdx.x;
    const int bn = blockIdx.x & 3;
    const int bm = blockIdx.x >> 2;
    const int row0 = bm << 7;
    const int n0 = bn << 7;
    const int mt = tid >> 4;
    const int nt = tid & 15;

    unsigned long long acc[4][8];
#pragma unroll
    for (int p = 0; p < 4; p++)
#pragma unroll
        for (int j = 0; j < 8; j++) acc[p][j] = 0ULL;

    for (int kt = 0; kt < 512; kt += 16) {
#pragma unroll
        for (int it = 0; it < 2; it++) {
            int idx = tid + (it << 8);
            int m = idx >> 2;
            int kq = (idx & 3) << 2;
            float4 v = *(const float4*)(x + (size_t)(row0 + m) * 512 + kt + kq);
            Ast[kq + 0][m] = v.x;
            Ast[kq + 1][m] = v.y;
            Ast[kq + 2][m] = v.z;
            Ast[kq + 3][m] = v.w;
        }
#pragma unroll
        for (int it = 0; it < 2; it++) {
            int idx = tid + (it << 8);
            int k = idx >> 5;
            int nq = (idx & 31) << 2;
            *(float4*)(&Bs[k][nq]) =
                *(const float4*)(W + (size_t)(kt + k) * 512 + n0 + nq);
        }
        __syncthreads();
#pragma unroll
        for (int k = 0; k < 16; k++) {
            ulonglong2 aA = *(const ulonglong2*)(&Ast[k][4 * mt]);
            ulonglong2 aB = *(const ulonglong2*)(&Ast[k][64 + 4 * mt]);
            float4 b0 = *(const float4*)(&Bs[k][4 * nt]);
            float4 b1 = *(const float4*)(&Bs[k][64 + 4 * nt]);
            unsigned long long bb[8];
            PACK2(bb[0], b0.x, b0.x);
            PACK2(bb[1], b0.y, b0.y);
            PACK2(bb[2], b0.z, b0.z);
            PACK2(bb[3], b0.w, b0.w);
            PACK2(bb[4], b1.x, b1.x);
            PACK2(bb[5], b1.y, b1.y);
            PACK2(bb[6], b1.z, b1.z);
            PACK2(bb[7], b1.w, b1.w);
#pragma unroll
            for (int j = 0; j < 8; j++) {
                FMA2(acc[0][j], aA.x, bb[j], acc[0][j]);
                FMA2(acc[1][j], aA.y, bb[j], acc[1][j]);
                FMA2(acc[2][j], aB.x, bb[j], acc[2][j]);
                FMA2(acc[3][j], aB.y, bb[j], acc[3][j]);
            }
        }
        __syncthreads();
    }

    float bv[8];
#pragma unroll
    for (int j = 0; j < 4; j++) {
        bv[j] = bias[n0 + 4 * nt + j];
        bv[4 + j] = bias[n0 + 64 + 4 * nt + j];
    }
    float res[8][8];
#pragma unroll
    for (int p = 0; p < 4; p++)
#pragma unroll
        for (int j = 0; j < 8; j++) {
            float lo, hi;
            UNPACK2(lo, hi, acc[p][j]);
            res[2 * p][j] = lo + bv[j];
            res[2 * p + 1][j] = hi + bv[j];
        }
#pragma unroll
    for (int rI = 0; rI < 8; rI++) {
        int lrow = (rI < 4) ? (4 * mt + rI) : (64 + 4 * mt + (rI - 4));
        size_t base = (size_t)(row0 + lrow) * 512 + n0;
        float4 s0 = make_float4(res[rI][0], res[rI][1], res[rI][2], res[rI][3]);
        float4 s1 = make_float4(res[rI][4], res[rI][5], res[rI][6], res[rI][7]);
        *(float4*)(g_xw + base + 4 * nt) = s0;
        *(float4*)(g_xw + base + 64 + 4 * nt) = s1;
    }
}

// ---------------------------------------------------------------------------
// Phase 2 smem layout (static, ~41.5 KB):
//   slab[2][8][64][4]  : pushed h, [buf][producer][feature][row]   16 KB
//   dupA/dupB[8][64][4]: per-warp {h,h} broadcast expansion        16 KB
//   red  u64[8][4][66] : k-chunk partials {c_even,c_odd}           8.25KB
//   stage[64][4]       : h(t+1) staging for vector pushes          1 KB
//   mbar[2][8]         : per-(buf,producer) mbarriers              128 B
// ---------------------------------------------------------------------------
__global__ __launch_bounds__(256, 1) __cluster_dims__(8, 1, 1)
void rnn_scan(const float* __restrict__ W, float* __restrict__ out) {
    __shared__ __align__(16) float slab[2][8][64][4];
    __shared__ __align__(16) float dupA[8][64][4];
    __shared__ __align__(16) float dupB[8][64][4];
    __shared__ __align__(16) unsigned long long red[8][4][66];
    __shared__ __align__(16) float stage[64][4];
    __shared__ __align__(8) unsigned long long mbar[2][8];

    const int bid = blockIdx.x;
    const int g = bid >> 3;   // group 0..15
    const int r0 = g << 2;    // 4 batch rows
    const int tid = threadIdx.x;
    const int cp = tid & 31;  // col-pair lane
    const int ks = tid >> 5;  // warp id == producer watched

    uint32_t rank;
    asm("mov.u32 %0, %%cluster_ctarank;" : "=r"(rank));
    const int c0 = ((int)rank) << 6;  // 64 cols per CTA

    // ---- init mbarriers + preset expect for first pushes (-> mbar[1]) ----
    uint32_t mb_base;
    asm("{ .reg .u64 t; cvta.to.shared.u64 t, %1; cvt.u32.u64 %0, t; }"
        : "=r"(mb_base)
        : "l"((void*)&mbar[0][0]));
    if (tid < 16) {
        asm volatile("mbarrier.init.shared.b64 [%0], %1;" ::"r"(
                         mb_base + tid * 8),
                     "r"(1u)
                     : "memory");
    }
    __syncthreads();
    if (tid < 8) {
        // mbar[1][tid]: receives 1KB from producer `tid` during t=0 epilogue
        asm volatile(
            "mbarrier.arrive.expect_tx.shared.b64 _, [%0], %1;" ::"r"(
                mb_base + (8 + tid) * 8),
            "r"(1024u)
            : "memory");
    }
    __syncthreads();
    asm volatile("barrier.cluster.arrive.aligned;" ::: "memory");
    asm volatile("barrier.cluster.wait.aligned;" ::: "memory");

    // ---- remote base addresses (slab + mbar) for all 8 peers ----
    uint32_t slab_base;
    asm("{ .reg .u64 t; cvta.to.shared.u64 t, %1; cvt.u32.u64 %0, t; }"
        : "=r"(slab_base)
        : "l"((void*)&slab[0][0][0][0]));
    uint32_t peer_slab[8], peer_mbar[8];
#pragma unroll
    for (int rk = 0; rk < 8; rk++) {
        asm("mapa.shared::cluster.u32 %0, %1, %2;"
            : "=r"(peer_slab[rk])
            : "r"(slab_base), "r"(rk));
        asm("mapa.shared::cluster.u32 %0, %1, %2;"
            : "=r"(peer_mbar[rk])
            : "r"(mb_base), "r"(rk));
    }

    // my wait mbar (warp ks): &mbar[b][ks]
    const uint32_t my_mb0 = mb_base + ks * 8;        // buf 0
    const uint32_t my_mb1 = mb_base + (8 + ks) * 8;  // buf 1

    // Wh slice: wpk[j] = {W[512+64ks+j][c0+2cp], W[512+64ks+j][c0+2cp+1]}
    unsigned long long wpk[64];
#pragma unroll
    for (int j = 0; j < 64; j++) {
        float2 w2 = *(const float2*)&W[(size_t)(512 + (ks << 6) + j) * 512 +
                                       c0 + (cp << 1)];
        PACK2(wpk[j], w2.x, w2.y);
    }

    const int rr = tid >> 6;  // epilogue row 0..3
    const int cc = tid & 63;  // epilogue col 0..63

    // push-role: thread handles (feature, half) = (tid>>2.., see below), 4 peers
    const int p_slot = tid >> 1;         // 0..127: feature*2+half
    const int p_feat = p_slot >> 1;      // 0..63
    const int p_half = p_slot & 1;       // rows 0-1 or 2-3
    const int p_rk0 = (tid & 1) << 2;    // peers 0-3 or 4-7
    // byte offset inside peer slab: [b2][rank][feat] + half*8
    const uint32_t p_off_base =
        (uint32_t)(rank * 1024 + p_feat * 16 + p_half * 8);

    unsigned int ph0 = 0, ph1 = 0;  // wait parity per buffer

    for (int t = 0; t < 1024; t++) {
        const int b = t & 1;
        // xw prefetch — overlaps wait + dup + mainloop
        float xwv =
            g_xw[((size_t)(r0 + rr) * 1024 + (size_t)t) * 512 + c0 + cc];

        unsigned long long a0 = 0ULL, a1 = 0ULL, a2 = 0ULL, a3 = 0ULL;
        if (t > 0) {
            // ---- wait local mbar[b][ks] (cta-scope acquire, no L1 flush) --
            const uint32_t mb = b ? my_mb1 : my_mb0;
            const unsigned int ph = b ? ph1 : ph0;
            unsigned int done;
            do {
                asm volatile(
                    "{\n\t.reg .pred p;\n\t"
                    "mbarrier.try_wait.parity.acquire.cta.shared::cta.b64 "
                    "p, [%1], %2, 0x989680;\n\t"
                    "selp.b32 %0, 1, 0, p;\n\t}"
                    : "=r"(done)
                    : "r"(mb), "r"(ph)
                    : "memory");
            } while (!done);
            if (b) ph1 ^= 1; else ph0 ^= 1;

            // ---- dup-pass: expand {h0..h3} -> {h,h} broadcast form -------
#pragma unroll
            for (int q = 0; q < 2; q++) {
                int j = cp + (q << 5);
                float4 v = *(const float4*)&slab[b][ks][j][0];
                *(float4*)&dupA[ks][j][0] = make_float4(v.x, v.x, v.y, v.y);
                *(float4*)&dupB[ks][j][0] = make_float4(v.z, v.z, v.w, v.w);
            }
            __syncwarp();

            // ---- mainloop: 64 x (2 LDS.128 broadcast + 4 FFMA2) ----------
#pragma unroll
            for (int j = 0; j < 64; j++) {
                ulonglong2 h01 = *(const ulonglong2*)&dupA[ks][j][0];
                ulonglong2 h23 = *(const ulonglong2*)&dupB[ks][j][0];
                FMA2(a0, h01.x, wpk[j], a0);  // row 0 {c_e,c_o}
                FMA2(a1, h01.y, wpk[j], a1);  // row 1
                FMA2(a2, h23.x, wpk[j], a2);  // row 2
                FMA2(a3, h23.y, wpk[j], a3);  // row 3
            }
        }
        // ---- cross-k-chunk reduction --------------------------------------
        red[ks][0][cp] = a0;
        red[ks][1][cp] = a1;
        red[ks][2][cp] = a2;
        red[ks][3][cp] = a3;
        __syncthreads();

        unsigned long long s2 = red[0][rr][cc >> 1];
#pragma unroll
        for (int q = 1; q < 8; q++) ADDF2(s2, s2, red[q][rr][cc >> 1]);
        float slo, shi;
        UNPACK2(slo, shi, s2);
        float v = tanhf(xwv + ((cc & 1) ? shi : slo));

        out[((size_t)(r0 + rr) * 1024 + (size_t)t) * 512 + c0 + cc] = v;

        if (t < 1023) {
            const int b2 = (t + 1) & 1;
            stage[cc][rr] = v;
            if (tid < 8) {
                // re-arm mbar[b][tid] for its next use (step t+2)
                asm volatile(
                    "mbarrier.arrive.expect_tx.shared.b64 _, [%0], %1;" ::"r"(
                        mb_base + (b * 8 + tid) * 8),
                    "r"(1024u)
                    : "memory");
            }
            __syncthreads();  // stage complete + expects armed + red[] safe

            // ---- push h(t+1): 4 x st.async.b64 per thread ----------------
            unsigned long long pv =
                *(const unsigned long long*)&stage[p_feat][p_half << 1];
            const uint32_t doff = (uint32_t)(b2 * 8192) + p_off_base;
            const uint32_t moff = (uint32_t)((b2 * 8 + (int)rank) * 8);
#pragma unroll
            for (int q = 0; q < 4; q++) {
                int rk = p_rk0 + q;
                asm volatile(
                    "st.async.shared::cluster.mbarrier::complete_tx::bytes"
                    ".b64 [%0], %1, [%2];" ::"r"(peer_slab[rk] + doff),
                    "l"(pv), "r"(peer_mbar[rk] + moff)
                    : "memory");
            }
        }
    }
}

// ---------------------------------------------------------------------------
extern "C" void kernel_launch(void* const* d_in, const int* in_sizes, int n_in,
                              void* d_out, int out_size) {
    const float* x = (const float*)d_in[0];  // (64, 1024, 512) f32
    const float* W = (const float*)d_in[1];  // (1024, 512) f32
    const float* b = (const float*)d_in[2];  // (512,) f32
    float* out = (float*)d_out;              // (64, 1024, 512) f32

    xw_gemm<<<2048, 256>>>(x, W, b);
    rnn_scan<<<128, 256>>>(W, out);
}

// round 7
// speedup vs baseline: 1.6994x; 1.4318x over previous
#include <cuda_runtime.h>
#include <math.h>
#include <stdint.h>

// Problem: B=64, T=1024, D=512, H=512
//   xw = x @ W[:512] + b              (65536x512x512 GEMM)
//   h_t = tanh(xw_t + h_{t-1} @ Wh)   scan over T=1024
//
// Phase 1: FFMA2 (packed f32x2) tiled GEMM -> g_xw scratch
// Phase 2: 16 groups x 8 CTAs (no clusters). CTA = 4 rows x 64 cols.
//   h exchange through L2 as SELF-VALIDATING 8B atoms {f32 value, u32 tag}
//   via relaxed b64 atomics: no flags, no fences, no L1 flushes, no
//   publish barrier. Consumer warps poll their 8 slots (MLP=8) until
//   tag == t, then compute. One __syncthreads per step (double-buffered
//   reduction scratch).

__device__ float g_xw[64u * 1024u * 512u];  // 128 MB scratch: [b][t][h]
// [buf][group][producerCTA][feature(64)][row(4)] : {f32 val, u32 tag}
__device__ unsigned long long g_hx[2][16][8][64][4];  // 512 KB

#define FMA2(d, a, b, c) \
    asm("fma.rn.f32x2 %0, %1, %2, %3;" : "=l"(d) : "l"(a), "l"(b), "l"(c))
#define ADDF2(d, a, b) \
    asm("add.rn.f32x2 %0, %1, %2;" : "=l"(d) : "l"(a), "l"(b))
#define PACK2(d, lo, hi) \
    asm("mov.b64 %0, {%1, %2;}" : "=l"(d) : "f"(lo), "f"(hi))
#undef PACK2
#define PACK2(d, lo, hi) \
    asm("mov.b64 %0, {%1, %2};" : "=l"(d) : "f"(lo), "f"(hi))
#define UNPACK2(lo, hi, v) \
    asm("mov.b64 {%0, %1}, %2;" : "=f"(lo), "=f"(hi) : "l"(v))

// ---------------------------------------------------------------------------
// Phase 1: g_xw[m][n] = sum_k x[m][k] * W[k][n] + b[n]
// ---------------------------------------------------------------------------
__global__ __launch_bounds__(256) void xw_gemm(const float* __restrict__ x,
                                               const float* __restrict__ W,
                                               const float* __restrict__ bias) {
    __shared__ __align__(16) float Ast[16][132];
    __shared__ __align__(16) float Bs[16][128];

    const int tid = threadIdx.x;
    const int bn = blockIdx.x & 3;
    const int bm = blockIdx.x >> 2;
    const int row0 = bm << 7;
    const int n0 = bn << 7;
    const int mt = tid >> 4;
    const int nt = tid & 15;

    unsigned long long acc[4][8];
#pragma unroll
    for (int p = 0; p < 4; p++)
#pragma unroll
        for (int j = 0; j < 8; j++) acc[p][j] = 0ULL;

    for (int kt = 0; kt < 512; kt += 16) {
#pragma unroll
        for (int it = 0; it < 2; it++) {
            int idx = tid + (it << 8);
            int m = idx >> 2;
            int kq = (idx & 3) << 2;
            float4 v = *(const float4*)(x + (size_t)(row0 + m) * 512 + kt + kq);
            Ast[kq + 0][m] = v.x;
            Ast[kq + 1][m] = v.y;
            Ast[kq + 2][m] = v.z;
            Ast[kq + 3][m] = v.w;
        }
#pragma unroll
        for (int it = 0; it < 2; it++) {
            int idx = tid + (it << 8);
            int k = idx >> 5;
            int nq = (idx & 31) << 2;
            *(float4*)(&Bs[k][nq]) =
                *(const float4*)(W + (size_t)(kt + k) * 512 + n0 + nq);
        }
        __syncthreads();
#pragma unroll
        for (int k = 0; k < 16; k++) {
            ulonglong2 aA = *(const ulonglong2*)(&Ast[k][4 * mt]);
            ulonglong2 aB = *(const ulonglong2*)(&Ast[k][64 + 4 * mt]);
            float4 b0 = *(const float4*)(&Bs[k][4 * nt]);
            float4 b1 = *(const float4*)(&Bs[k][64 + 4 * nt]);
            unsigned long long bb[8];
            PACK2(bb[0], b0.x, b0.x);
            PACK2(bb[1], b0.y, b0.y);
            PACK2(bb[2], b0.z, b0.z);
            PACK2(bb[3], b0.w, b0.w);
            PACK2(bb[4], b1.x, b1.x);
            PACK2(bb[5], b1.y, b1.y);
            PACK2(bb[6], b1.z, b1.z);
            PACK2(bb[7], b1.w, b1.w);
#pragma unroll
            for (int j = 0; j < 8; j++) {
                FMA2(acc[0][j], aA.x, bb[j], acc[0][j]);
                FMA2(acc[1][j], aA.y, bb[j], acc[1][j]);
                FMA2(acc[2][j], aB.x, bb[j], acc[2][j]);
                FMA2(acc[3][j], aB.y, bb[j], acc[3][j]);
            }
        }
        __syncthreads();
    }

    float bv[8];
#pragma unroll
    for (int j = 0; j < 4; j++) {
        bv[j] = bias[n0 + 4 * nt + j];
        bv[4 + j] = bias[n0 + 64 + 4 * nt + j];
    }
    float res[8][8];
#pragma unroll
    for (int p = 0; p < 4; p++)
#pragma unroll
        for (int j = 0; j < 8; j++) {
            float lo, hi;
            UNPACK2(lo, hi, acc[p][j]);
            res[2 * p][j] = lo + bv[j];
            res[2 * p + 1][j] = hi + bv[j];
        }
#pragma unroll
    for (int rI = 0; rI < 8; rI++) {
        int lrow = (rI < 4) ? (4 * mt + rI) : (64 + 4 * mt + (rI - 4));
        size_t base = (size_t)(row0 + lrow) * 512 + n0;
        float4 s0 = make_float4(res[rI][0], res[rI][1], res[rI][2], res[rI][3]);
        float4 s1 = make_float4(res[rI][4], res[rI][5], res[rI][6], res[rI][7]);
        *(float4*)(g_xw + base + 4 * nt) = s0;
        *(float4*)(g_xw + base + 64 + 4 * nt) = s1;
    }
}

// ---------------------------------------------------------------------------
// zero the tag arena (must run each replay so stale tags never match)
// ---------------------------------------------------------------------------
__global__ void init_hx() {
    unsigned long long* p = &g_hx[0][0][0][0][0];
    int i = blockIdx.x * blockDim.x + threadIdx.x;
#pragma unroll
    for (int q = 0; q < 4; q++) p[i + q * 16384] = 0ULL;
}

// ---------------------------------------------------------------------------
// Phase 2: tagged-value scan. CTA (g = bid>>3, s = bid&7): rows r0=4g,
//   cols c0=64s. Warp ks consumes producer CTA (g, ks)'s 64-feature chunk.
//   Poll 8 slots/lane until tag==t -> dup-expand to smem -> 64-iter FMA2 ->
//   one barrier -> k-reduce -> tanh -> STG out + tagged h store (no barrier,
//   no fence).
// ---------------------------------------------------------------------------
__global__ __launch_bounds__(256, 1) void rnn_scan(const float* __restrict__ W,
                                                   float* __restrict__ out) {
    __shared__ __align__(16) float dupA[8][64][4];             // 8 KB
    __shared__ __align__(16) float dupB[8][64][4];             // 8 KB
    __shared__ __align__(16) unsigned long long red[2][8][4][66];  // 33 KB

    const int bid = blockIdx.x;
    const int g = bid >> 3;   // group 0..15
    const int r0 = g << 2;    // 4 batch rows
    const int s = bid & 7;    // col split 0..7
    const int c0 = s << 6;    // 64 feature cols
    const int tid = threadIdx.x;
    const int cp = tid & 31;  // col-pair lane
    const int ks = tid >> 5;  // warp id == producer CTA watched

    // Wh slice: wpk[j] = {W[512+64ks+j][c0+2cp], W[512+64ks+j][c0+2cp+1]}
    unsigned long long wpk[64];
#pragma unroll
    for (int j = 0; j < 64; j++) {
        float2 w2 = *(const float2*)&W[(size_t)(512 + (ks << 6) + j) * 512 +
                                       c0 + (cp << 1)];
        PACK2(wpk[j], w2.x, w2.y);
    }

    const int rr = tid >> 6;  // epilogue row 0..3
    const int cc = tid & 63;  // epilogue col 0..63

    // poll sources: slots [buf][g][ks][cp][0..3] and [cp+32][0..3]
    unsigned long long* const src0 = &g_hx[0][g][ks][cp][0];
    unsigned long long* const src1 = &g_hx[0][g][ks][cp + 32][0];
    const size_t bufstride = 16 * 8 * 64 * 4;  // u64s per buffer

    // publish target: [buf][g][s][cc][rr]
    unsigned long long* const dst = &g_hx[0][g][s][cc][rr];

    for (int t = 0; t < 1024; t++) {
        const int pb = t & 1;
        // xw prefetch — overlaps poll + dup + mainloop
        float xwv =
            g_xw[((size_t)(r0 + rr) * 1024 + (size_t)t) * 512 + c0 + cc];

        unsigned long long a0 = 0ULL, a1 = 0ULL, a2 = 0ULL, a3 = 0ULL;
        if (t > 0) {
            const unsigned long long* p0 = src0 + (size_t)pb * bufstride;
            const unsigned long long* p1 = src1 + (size_t)pb * bufstride;
            const unsigned int tg = (unsigned int)t;
            unsigned long long sv[8];
#pragma unroll
            for (int i = 0; i < 4; i++) {
                asm volatile("ld.relaxed.gpu.global.b64 %0, [%1];"
                             : "=l"(sv[i]) : "l"(p0 + i) : "memory");
                asm volatile("ld.relaxed.gpu.global.b64 %0, [%1];"
                             : "=l"(sv[4 + i]) : "l"(p1 + i) : "memory");
            }
            bool ok;
            do {
                ok = true;
#pragma unroll
                for (int i = 0; i < 4; i++) {
                    if ((unsigned int)(sv[i] >> 32) != tg) {
                        asm volatile("ld.relaxed.gpu.global.b64 %0, [%1];"
                                     : "=l"(sv[i]) : "l"(p0 + i) : "memory");
                        ok = false;
                    }
                    if ((unsigned int)(sv[4 + i] >> 32) != tg) {
                        asm volatile("ld.relaxed.gpu.global.b64 %0, [%1];"
                                     : "=l"(sv[4 + i]) : "l"(p1 + i)
                                     : "memory");
                        ok = false;
                    }
                }
            } while (!ok);

            // dup-expand {h0..h3} -> {h,h} broadcast form
            float h0 = __uint_as_float((unsigned int)sv[0]);
            float h1 = __uint_as_float((unsigned int)sv[1]);
            float h2 = __uint_as_float((unsigned int)sv[2]);
            float h3 = __uint_as_float((unsigned int)sv[3]);
            *(float4*)&dupA[ks][cp][0] = make_float4(h0, h0, h1, h1);
            *(float4*)&dupB[ks][cp][0] = make_float4(h2, h2, h3, h3);
            h0 = __uint_as_float((unsigned int)sv[4]);
            h1 = __uint_as_float((unsigned int)sv[5]);
            h2 = __uint_as_float((unsigned int)sv[6]);
            h3 = __uint_as_float((unsigned int)sv[7]);
            *(float4*)&dupA[ks][cp + 32][0] = make_float4(h0, h0, h1, h1);
            *(float4*)&dupB[ks][cp + 32][0] = make_float4(h2, h2, h3, h3);
            __syncwarp();

            // mainloop: 64 x (2 LDS.128 broadcast + 4 FFMA2)
#pragma unroll
            for (int j = 0; j < 64; j++) {
                ulonglong2 h01 = *(const ulonglong2*)&dupA[ks][j][0];
                ulonglong2 h23 = *(const ulonglong2*)&dupB[ks][j][0];
                FMA2(a0, h01.x, wpk[j], a0);  // row 0 {c_e,c_o}
                FMA2(a1, h01.y, wpk[j], a1);  // row 1
                FMA2(a2, h23.x, wpk[j], a2);  // row 2
                FMA2(a3, h23.y, wpk[j], a3);  // row 3
            }
        }
        // cross-k-chunk reduction (double-buffered -> one barrier per step)
        red[pb][ks][0][cp] = a0;
        red[pb][ks][1][cp] = a1;
        red[pb][ks][2][cp] = a2;
        red[pb][ks][3][cp] = a3;
        __syncthreads();

        unsigned long long s2 = red[pb][0][rr][cc >> 1];
#pragma unroll
        for (int q = 1; q < 8; q++) ADDF2(s2, s2, red[pb][q][rr][cc >> 1]);
        float slo, shi;
        UNPACK2(slo, shi, s2);
        float v = tanhf(xwv + ((cc & 1) ? shi : slo));

        out[((size_t)(r0 + rr) * 1024 + (size_t)t) * 512 + c0 + cc] = v;

        if (t < 1023) {
            // publish tagged h immediately — no barrier, no fence
            unsigned long long pkt =
                ((unsigned long long)(unsigned int)(t + 1) << 32) |
                (unsigned long long)__float_as_uint(v);
            unsigned long long* d =
                dst + (size_t)((t + 1) & 1) * bufstride;
            asm volatile("st.relaxed.gpu.global.b64 [%0], %1;" ::"l"(d),
                         "l"(pkt)
                         : "memory");
        }
    }
}

// ---------------------------------------------------------------------------
extern "C" void kernel_launch(void* const* d_in, const int* in_sizes, int n_in,
                              void* d_out, int out_size) {
    const float* x = (const float*)d_in[0];  // (64, 1024, 512) f32
    const float* W = (const float*)d_in[1];  // (1024, 512) f32
    const float* b = (const float*)d_in[2];  // (512,) f32
    float* out = (float*)d_out;              // (64, 1024, 512) f32

    xw_gemm<<<2048, 256>>>(x, W, b);
    init_hx<<<64, 256>>>();
    rnn_scan<<<128, 256>>>(W, out);
}